// round 13
// baseline (speedup 1.0000x reference)
#include <cuda_runtime.h>
#include <cuda_fp16.h>
#include <cstdint>

#define NT 128
#define BM 128
#define BN 64
#define DH 128
#define HCONST 16
#define NKV 32            // S/BN for S=2048

// ---- SMEM byte layout (main kernel) ----
#define QH_OFF 0                 // Q fp16: 128 rows x 256B (swizzled)
#define BUF0   32768
#define KH_O   0                 // K fp16: 64 x 256B (swizzled)
#define VTH_O  16384             // V^T fp16: 128 d-rows x 144B (padded)
#define BUFSZ  34816
#define SMEM_TOTAL (BUF0 + 2 * BUFSZ)   // 102400 B -> 2 CTAs/SM
#define KREG_BYTES 16384
#define VREG_BYTES 18432

// 1/sqrt(128) * log2(e)
#define SCALE2 0.1275200917303861f

// Precomputed KV tile images: [B][H][NKV] x BUFSZ bytes, same layout as smem buffer
__device__ __align__(128) char g_kv[2 * HCONST * NKV * (size_t)BUFSZ];

__device__ __forceinline__ uint32_t smem_u32(const void* p) {
    uint32_t a;
    asm("{ .reg .u64 t; cvta.to.shared.u64 t, %1; cvt.u32.u64 %0, t; }" : "=r"(a) : "l"(p));
    return a;
}
__device__ __forceinline__ void ldsm4(uint32_t r[4], uint32_t addr) {
    asm volatile("ldmatrix.sync.aligned.m8n8.x4.shared.b16 {%0,%1,%2,%3}, [%4];"
                 : "=r"(r[0]), "=r"(r[1]), "=r"(r[2]), "=r"(r[3]) : "r"(addr));
}
__device__ __forceinline__ void mma16816(float c[4], const uint32_t a[4], const uint32_t b[2]) {
    asm volatile("mma.sync.aligned.m16n8k16.row.col.f32.f16.f16.f32 "
                 "{%0,%1,%2,%3}, {%4,%5,%6,%7}, {%8,%9}, {%0,%1,%2,%3};"
                 : "+f"(c[0]), "+f"(c[1]), "+f"(c[2]), "+f"(c[3])
                 : "r"(a[0]), "r"(a[1]), "r"(a[2]), "r"(a[3]), "r"(b[0]), "r"(b[1]));
}
__device__ __forceinline__ float ex2f(float x) {
    float y; asm("ex2.approx.f32 %0, %1;" : "=f"(y) : "f"(x)); return y;
}
__device__ __forceinline__ void cp16(uint32_t saddr, const char* g) {
    asm volatile("cp.async.cg.shared.global [%0], [%1], 16;" :: "r"(saddr), "l"(g));
}
#define CP_COMMIT() asm volatile("cp.async.commit_group;" ::: "memory")
#define CP_WAIT0()  asm volatile("cp.async.wait_group 0;" ::: "memory")
#define CP_WAIT1()  asm volatile("cp.async.wait_group 1;" ::: "memory")

// Copy BYTES from gmem image to smem (multiples of 2048; NT*16 = 2048).
template <int BYTES>
__device__ __forceinline__ void copy_img(uint32_t sdst, const char* g, int tid) {
    #pragma unroll
    for (int o = 0; o + NT * 16 <= BYTES; o += NT * 16)
        cp16(sdst + o + tid * 16, g + o + tid * 16);
    if constexpr (BYTES % (NT * 16) != 0) {
        constexpr int o = (BYTES / (NT * 16)) * (NT * 16);
        if (tid < (BYTES - o) / 16)
            cp16(sdst + o + tid * 16, g + o + tid * 16);
    }
}

__device__ __forceinline__ uint32_t pack_h2(float x, float y) {
    __half2 v = __floats2half2_rn(x, y);
    return *(uint32_t*)&v;
}

// ---- tile-image store helpers (prepass, 256 threads) ----
#define PNT 256
__device__ __forceinline__ void img_k_one(char* kdst, float4 v, int idx) {
    int r = idx >> 5, c4 = idx & 31;
    uint32_t w0 = pack_h2(v.x, v.y);
    uint32_t w1 = pack_h2(v.z, v.w);
    uint32_t o = (uint32_t)r * 256 + ((((uint32_t)(c4 >> 1)) ^ (r & 7)) << 4) + (c4 & 1) * 8;
    *(uint2*)(kdst + KH_O + o) = make_uint2(w0, w1);
}
__device__ __forceinline__ void img_v_pair(char* vdst, float4 v0, float4 v1, int idx) {
    int a = idx & 31, dc = idx >> 5;
    const float* e0 = (const float*)&v0;
    const float* e1 = (const float*)&v1;
    #pragma unroll
    for (int i = 0; i < 4; i++) {
        uint32_t w = pack_h2(e0[i], e1[i]);
        uint32_t o = (uint32_t)(dc * 4 + i) * 144 + a * 4;
        *(uint32_t*)(vdst + VTH_O + o) = w;
    }
}

// ================= prepass: K,V fp32 -> fp16 tile images =================
__global__ void __launch_bounds__(PNT, 4)
kv_prepass(const float* __restrict__ K, const float* __restrict__ V, int S, int H)
{
    const int t = blockIdx.x, h = blockIdx.y, b = blockIdx.z;
    const int tid = threadIdx.x;
    const int rs = H * DH;
    char* img = g_kv + ((size_t)((b * HCONST + h) * NKV + t)) * BUFSZ;
    const float* kg = K + ((size_t)(b * S + t * BN)) * rs + (size_t)h * DH;
    const float* vg = V + ((size_t)(b * S + t * BN)) * rs + (size_t)h * DH;
    #pragma unroll
    for (int it = 0; it < 8; it++) {
        int idx = tid + PNT * it;                // 0..2047
        int r = idx >> 5, c4 = idx & 31;
        img_k_one(img, *(const float4*)(kg + (size_t)r * rs + c4 * 4), idx);
    }
    #pragma unroll
    for (int it = 0; it < 4; it++) {
        int idx = tid + PNT * it;                // 0..1023
        int a = idx & 31, dc = idx >> 5;
        float4 v0 = *(const float4*)(vg + (size_t)(2 * a) * rs + dc * 4);
        float4 v1 = *(const float4*)(vg + (size_t)(2 * a + 1) * rs + dc * 4);
        img_v_pair(img, v0, v1, idx);
    }
}

// ---- MMA sub-blocks (M=32 per warp) ----
// QK ks-block: 2 Q ldsm + 4 K ldsm + 16 MMAs
__device__ __forceinline__ void qk_ks(float sacc[2][8][4], uint32_t qoffH0, uint32_t kb_,
                                      int ks, uint32_t swz, uint32_t hiA, uint32_t kh8)
{
    uint32_t qh0[4], qh1[4];
    uint32_t qsw = (((((uint32_t)ks << 1) | hiA) ^ swz) << 4);
    ldsm4(qh0, qoffH0 + qsw);
    ldsm4(qh1, qoffH0 + 16 * 256 + qsw);
    const uint32_t kch = (((((uint32_t)ks << 1) | kh8) ^ swz) << 4);
    #pragma unroll
    for (int t = 0; t < 4; t++) {
        uint32_t kh[4];
        ldsm4(kh, kb_ + (uint32_t)t * 4096 + kch);
        mma16816(sacc[0][2*t],   qh0, kh);   mma16816(sacc[0][2*t+1], qh0, kh+2);
        mma16816(sacc[1][2*t],   qh1, kh);   mma16816(sacc[1][2*t+1], qh1, kh+2);
    }
}
// PV s-block: 8 V ldsm + 32 MMAs
__device__ __forceinline__ void pv_s(float oacc[2][16][4], const uint32_t pF[2][16],
                                     uint32_t vb_, int s)
{
    #pragma unroll
    for (int u = 0; u < 8; u++) {
        uint32_t vh[4];
        ldsm4(vh, vb_ + (uint32_t)u * 2304 + (uint32_t)s * 32);
        mma16816(oacc[0][2*u],   pF[0] + 4*s, vh);   mma16816(oacc[0][2*u+1], pF[0] + 4*s, vh+2);
        mma16816(oacc[1][2*u],   pF[1] + 4*s, vh);   mma16816(oacc[1][2*u+1], pF[1] + 4*s, vh+2);
    }
}

// ---- softmax one m-half: 8 frags -> pF[m][16], l accumulation ----
__device__ __forceinline__ void softmax_m(const float sacc[8][4], uint32_t* pFm,
                                          float& la, float& lb, int n0, int r0m,
                                          bool causal, int lane)
{
    const bool needmask = causal && (n0 + BN - 1 > r0m);
    #pragma unroll
    for (int nt = 0; nt < 8; nt++) {
        float p0 = ex2f(sacc[nt][0]);
        float p1 = ex2f(sacc[nt][1]);
        float p2 = ex2f(sacc[nt][2]);
        float p3 = ex2f(sacc[nt][3]);
        if (needmask) {
            int c0 = n0 + 8 * nt + 2 * (lane & 3);
            if (c0 > r0m) p0 = 0.0f;
            if (c0 + 1 > r0m) p1 = 0.0f;
            if (c0 > r0m + 8) p2 = 0.0f;
            if (c0 + 1 > r0m + 8) p3 = 0.0f;
        }
        la += p0 + p1;
        lb += p2 + p3;
        pFm[2*nt]   = pack_h2(p0, p1);
        pFm[2*nt+1] = pack_h2(p2, p3);
    }
}

__global__ void __launch_bounds__(NT, 2)
fa_hmma10(const float* __restrict__ Q, const int* __restrict__ causal_flag,
          float* __restrict__ O, int S, int H)
{
    extern __shared__ char smem[];
    const uint32_t sb = smem_u32(smem);
    const int tid  = threadIdx.x;
    const int lane = tid & 31;
    const int wid  = tid >> 5;                      // 0..3, each owns 32 q-rows
    const int qi = gridDim.x - 1 - blockIdx.x;      // longest CTAs first
    const int h = blockIdx.y, b = blockIdx.z;
    const int q0 = qi * BM;
    const int rs = H * DH;
    const bool causal = (causal_flag[0] != 0);
    const int ntiles = causal ? 2 * (qi + 1) : (S / BN);

    const uint32_t swz = lane & 7;
    const uint32_t hiA = (uint32_t)lane >> 4;
    const uint32_t kh8 = ((uint32_t)lane >> 3) & 1;
    const uint32_t bnl = 8 * hiA + swz;
    const uint32_t qoffH0 = sb + QH_OFF + ((uint32_t)wid * 32 + (lane & 15)) * 256;
    const int r0 = q0 + wid * 32 + (lane >> 2);     // m0 rows: r0, r0+8; m1: r0+16, r0+24

    const char* kvbase = g_kv + ((size_t)((b * HCONST + h) * NKV)) * BUFSZ;

    // ---- issue tile0 + tile1 image copies ----
    copy_img<BUFSZ>(sb + BUF0, kvbase, tid);
    CP_COMMIT();
    copy_img<BUFSZ>(sb + BUF0 + BUFSZ, kvbase + BUFSZ, tid);
    CP_COMMIT();

    // ---- convert Q tile to fp16 (scale*log2e folded), overlaps copies ----
    {
        const float* qg = Q + ((size_t)(b * S + q0)) * rs + (size_t)h * DH;
        #pragma unroll
        for (int it = 0; it < 32; it++) {
            int idx = tid + NT * it;                 // 0..4095
            int r = idx >> 5, c4 = idx & 31;
            float4 v = *(const float4*)(qg + (size_t)r * rs + c4 * 4);
            uint32_t w0 = pack_h2(v.x * SCALE2, v.y * SCALE2);
            uint32_t w1 = pack_h2(v.z * SCALE2, v.w * SCALE2);
            uint32_t o = (uint32_t)r * 256 + ((((uint32_t)(c4 >> 1)) ^ (r & 7)) << 4) + (c4 & 1) * 8;
            *(uint2*)(smem + QH_OFF + o) = make_uint2(w0, w1);
        }
    }
    CP_WAIT0();
    __syncthreads();

    float oacc[2][16][4];
    #pragma unroll
    for (int m = 0; m < 2; m++)
        #pragma unroll
        for (int t = 0; t < 16; t++)
            #pragma unroll
            for (int e = 0; e < 4; e++) oacc[m][t][e] = 0.0f;
    float l[4] = {0.0f, 0.0f, 0.0f, 0.0f};
    uint32_t pF[2][16];
    float sacc[2][8][4];
    #pragma unroll
    for (int m = 0; m < 2; m++)
        #pragma unroll
        for (int t = 0; t < 8; t++)
            #pragma unroll
            for (int e = 0; e < 4; e++) sacc[m][t][e] = 0.0f;

    // ---- prologue: QK(0) ----
    {
        const uint32_t kb_ = sb + BUF0 + KH_O + bnl * 256;   // buf0
        #pragma unroll
        for (int ks = 0; ks < 8; ks++)
            qk_ks(sacc, qoffH0, kb_, ks, swz, hiA, kh8);
    }
    __syncthreads();   // all warps done with buf0.K before K(2) copy overwrites it

    // ---- main loop: iter j does softmax(j), then PV(j) || QK(j+1) ----
    for (int j = 0; j < ntiles - 1; j++) {
        const uint32_t vbuf = sb + BUF0 + (uint32_t)(j & 1) * BUFSZ;        // V(j); K(j+2)/V(j+2) dst
        const uint32_t kbuf = sb + BUF0 + (uint32_t)((j + 1) & 1) * BUFSZ;  // K(j+1)
        const uint32_t kb_ = kbuf + KH_O + bnl * 256;
        const uint32_t vb_ = vbuf + VTH_O + bnl * 144 + kh8 * 16;
        const bool more2 = (j + 2 < ntiles);
        const char* g2 = kvbase + (size_t)(j + 2) * BUFSZ;
        const int n0 = j * BN;

        // K(j+2) -> buf[j&1].K  (K(j) consumed by all warps last iteration; barrier passed)
        if (more2)
            copy_img<KREG_BYTES>(vbuf + KH_O, g2 + KH_O, tid);
        CP_COMMIT();

        // softmax(j): consumes sacc, fills pF; sacc then reusable for QK(j+1)
        softmax_m(sacc[0], pF[0], l[0], l[1], n0, r0,      causal, lane);
        softmax_m(sacc[1], pF[1], l[2], l[3], n0, r0 + 16, causal, lane);
        #pragma unroll
        for (int m = 0; m < 2; m++)
            #pragma unroll
            for (int t = 0; t < 8; t++)
                #pragma unroll
                for (int e = 0; e < 4; e++) sacc[m][t][e] = 0.0f;

        qk_ks(sacc, qoffH0, kb_, 0, swz, hiA, kh8);  pv_s(oacc, pF, vb_, 0);
        qk_ks(sacc, qoffH0, kb_, 1, swz, hiA, kh8);  pv_s(oacc, pF, vb_, 1);
        qk_ks(sacc, qoffH0, kb_, 2, swz, hiA, kh8);  pv_s(oacc, pF, vb_, 2);
        qk_ks(sacc, qoffH0, kb_, 3, swz, hiA, kh8);  pv_s(oacc, pF, vb_, 3);

        // === WAR fence: ALL warps must finish reading V(j) before V(j+2) stores issue ===
        __syncthreads();

        // V(j+2) -> buf[j&1].V (now quiescent)
        if (more2)
            copy_img<VREG_BYTES>(vbuf + VTH_O, g2 + VTH_O, tid);
        CP_COMMIT();

        qk_ks(sacc, qoffH0, kb_, 4, swz, hiA, kh8);
        qk_ks(sacc, qoffH0, kb_, 5, swz, hiA, kh8);
        qk_ks(sacc, qoffH0, kb_, 6, swz, hiA, kh8);
        qk_ks(sacc, qoffH0, kb_, 7, swz, hiA, kh8);

        CP_WAIT1();        // K(j+2) landed; V(j+2) may still fly (needed next-next iter)
        __syncthreads();
    }

    // ---- tail: softmax + PV of tile (ntiles-1) ----
    {
        const uint32_t vbuf = sb + BUF0 + (uint32_t)((ntiles - 1) & 1) * BUFSZ;
        const uint32_t vb_ = vbuf + VTH_O + bnl * 144 + kh8 * 16;
        const int n0 = (ntiles - 1) * BN;
        softmax_m(sacc[0], pF[0], l[0], l[1], n0, r0,      causal, lane);
        softmax_m(sacc[1], pF[1], l[2], l[3], n0, r0 + 16, causal, lane);
        pv_s(oacc, pF, vb_, 0);
        pv_s(oacc, pF, vb_, 1);
        pv_s(oacc, pF, vb_, 2);
        pv_s(oacc, pF, vb_, 3);
    }

    // ---- epilogue ----
    #pragma unroll
    for (int i = 0; i < 4; i++) {
        l[i] += __shfl_xor_sync(0xffffffffu, l[i], 1);
        l[i] += __shfl_xor_sync(0xffffffffu, l[i], 2);
    }
    const int cofs = 2 * (lane & 3);
    #pragma unroll
    for (int m = 0; m < 2; m++) {
        const float ia = 1.0f / l[2*m], ib = 1.0f / l[2*m + 1];
        float* oa = O + ((size_t)(b * S + r0 + 16*m)) * rs + (size_t)h * DH;
        float* ob = O + ((size_t)(b * S + r0 + 16*m + 8)) * rs + (size_t)h * DH;
        #pragma unroll
        for (int t = 0; t < 16; t++) {
            *(float2*)(oa + 8 * t + cofs) = make_float2(oacc[m][t][0] * ia, oacc[m][t][1] * ia);
            *(float2*)(ob + 8 * t + cofs) = make_float2(oacc[m][t][2] * ib, oacc[m][t][3] * ib);
        }
    }
}

extern "C" void kernel_launch(void* const* d_in, const int* in_sizes, int n_in,
                              void* d_out, int out_size) {
    const float* q = (const float*)d_in[0];
    const float* k = (const float*)d_in[1];
    const float* v = (const float*)d_in[2];
    const int* causal = (const int*)d_in[3];
    float* out = (float*)d_out;

    const int B = 2, H = 16, D = 128;
    const int S = in_sizes[0] / (B * H * D);   // 2048

    dim3 pgrid(S / BN, H, B);
    kv_prepass<<<pgrid, PNT>>>(k, v, S, H);

    cudaFuncSetAttribute(fa_hmma10, cudaFuncAttributeMaxDynamicSharedMemorySize, SMEM_TOTAL);
    dim3 grid(S / BM, H, B);
    fa_hmma10<<<grid, NT, SMEM_TOTAL>>>(q, causal, out, S, H);
}

// round 14
// speedup vs baseline: 1.1175x; 1.1175x over previous
#include <cuda_runtime.h>
#include <cuda_fp16.h>
#include <cstdint>

#define NT 128
#define BM 64
#define BN 64
#define DH 128
#define HCONST 16
#define NKV 32            // S/BN for S=2048

// ---- SMEM byte layout (main kernel) ----
#define QH_OFF 0                 // Q fp16: 64 rows x 256B (swizzled)
#define BUF0   16384
#define KH_O   0                 // K fp16: 64 x 256B (swizzled)
#define VTH_O  16384             // V^T fp16: 128 d-rows x 144B (padded)
#define BUFSZ  34816
#define SMEM_TOTAL (BUF0 + 2 * BUFSZ)   // 86016 B -> 2 CTAs/SM
#define KREG_BYTES 16384
#define VREG_BYTES 18432

// 1/sqrt(128) * log2(e)
#define SCALE2 0.1275200917303861f

// Precomputed KV tile images: [B][H][NKV] x BUFSZ bytes, same layout as smem buffer
__device__ __align__(128) char g_kv[2 * HCONST * NKV * (size_t)BUFSZ];

__device__ __forceinline__ uint32_t smem_u32(const void* p) {
    uint32_t a;
    asm("{ .reg .u64 t; cvta.to.shared.u64 t, %1; cvt.u32.u64 %0, t; }" : "=r"(a) : "l"(p));
    return a;
}
__device__ __forceinline__ void ldsm4(uint32_t r[4], uint32_t addr) {
    asm volatile("ldmatrix.sync.aligned.m8n8.x4.shared.b16 {%0,%1,%2,%3}, [%4];"
                 : "=r"(r[0]), "=r"(r[1]), "=r"(r[2]), "=r"(r[3]) : "r"(addr));
}
__device__ __forceinline__ void mma16816(float c[4], const uint32_t a[4], const uint32_t b[2]) {
    asm volatile("mma.sync.aligned.m16n8k16.row.col.f32.f16.f16.f32 "
                 "{%0,%1,%2,%3}, {%4,%5,%6,%7}, {%8,%9}, {%0,%1,%2,%3};"
                 : "+f"(c[0]), "+f"(c[1]), "+f"(c[2]), "+f"(c[3])
                 : "r"(a[0]), "r"(a[1]), "r"(a[2]), "r"(a[3]), "r"(b[0]), "r"(b[1]));
}
__device__ __forceinline__ float ex2f(float x) {
    float y; asm("ex2.approx.f32 %0, %1;" : "=f"(y) : "f"(x)); return y;
}
__device__ __forceinline__ void cp16(uint32_t saddr, const char* g) {
    asm volatile("cp.async.cg.shared.global [%0], [%1], 16;" :: "r"(saddr), "l"(g));
}
#define CP_COMMIT() asm volatile("cp.async.commit_group;" ::: "memory")
#define CP_WAIT0()  asm volatile("cp.async.wait_group 0;" ::: "memory")
#define CP_WAIT1()  asm volatile("cp.async.wait_group 1;" ::: "memory")

// Copy BYTES from gmem image to smem (NT*16 = 2048 per sweep).
template <int BYTES>
__device__ __forceinline__ void copy_img(uint32_t sdst, const char* g, int tid) {
    #pragma unroll
    for (int o = 0; o + NT * 16 <= BYTES; o += NT * 16)
        cp16(sdst + o + tid * 16, g + o + tid * 16);
    if constexpr (BYTES % (NT * 16) != 0) {
        constexpr int o = (BYTES / (NT * 16)) * (NT * 16);
        if (tid < (BYTES - o) / 16)
            cp16(sdst + o + tid * 16, g + o + tid * 16);
    }
}

__device__ __forceinline__ uint32_t pack_h2(float x, float y) {
    __half2 v = __floats2half2_rn(x, y);
    return *(uint32_t*)&v;
}

// ---- tile-image store helpers (prepass, 256 threads) ----
#define PNT 256
__device__ __forceinline__ void img_k_one(char* kdst, float4 v, int idx) {
    int r = idx >> 5, c4 = idx & 31;
    uint32_t w0 = pack_h2(v.x, v.y);
    uint32_t w1 = pack_h2(v.z, v.w);
    uint32_t o = (uint32_t)r * 256 + ((((uint32_t)(c4 >> 1)) ^ (r & 7)) << 4) + (c4 & 1) * 8;
    *(uint2*)(kdst + KH_O + o) = make_uint2(w0, w1);
}
__device__ __forceinline__ void img_v_pair(char* vdst, float4 v0, float4 v1, int idx) {
    int a = idx & 31, dc = idx >> 5;
    const float* e0 = (const float*)&v0;
    const float* e1 = (const float*)&v1;
    #pragma unroll
    for (int i = 0; i < 4; i++) {
        uint32_t w = pack_h2(e0[i], e1[i]);
        uint32_t o = (uint32_t)(dc * 4 + i) * 144 + a * 4;
        *(uint32_t*)(vdst + VTH_O + o) = w;
    }
}

// ================= prepass: K,V fp32 -> fp16 tile images =================
__global__ void __launch_bounds__(PNT, 4)
kv_prepass(const float* __restrict__ K, const float* __restrict__ V, int S, int H)
{
    const int t = blockIdx.x, h = blockIdx.y, b = blockIdx.z;
    const int tid = threadIdx.x;
    const int rs = H * DH;
    char* img = g_kv + ((size_t)((b * HCONST + h) * NKV + t)) * BUFSZ;
    const float* kg = K + ((size_t)(b * S + t * BN)) * rs + (size_t)h * DH;
    const float* vg = V + ((size_t)(b * S + t * BN)) * rs + (size_t)h * DH;
    #pragma unroll
    for (int it = 0; it < 8; it++) {
        int idx = tid + PNT * it;                // 0..2047
        int r = idx >> 5, c4 = idx & 31;
        img_k_one(img, *(const float4*)(kg + (size_t)r * rs + c4 * 4), idx);
    }
    #pragma unroll
    for (int it = 0; it < 4; it++) {
        int idx = tid + PNT * it;                // 0..1023
        int a = idx & 31, dc = idx >> 5;
        float4 v0 = *(const float4*)(vg + (size_t)(2 * a) * rs + dc * 4);
        float4 v1 = *(const float4*)(vg + (size_t)(2 * a + 1) * rs + dc * 4);
        img_v_pair(img, v0, v1, idx);
    }
}

// ---- MMA sub-blocks ----
// QK ks-block: Q from registers (qF), 4 K ldsm + 8 MMAs
__device__ __forceinline__ void qk_ks(float sacc[8][4], const uint32_t* qf, uint32_t kb_,
                                      int ks, uint32_t swz, uint32_t kh8)
{
    const uint32_t kch = (((((uint32_t)ks << 1) | kh8) ^ swz) << 4);
    #pragma unroll
    for (int t = 0; t < 4; t++) {
        uint32_t kh[4];
        ldsm4(kh, kb_ + (uint32_t)t * 4096 + kch);
        mma16816(sacc[2*t],   qf, kh);   mma16816(sacc[2*t+1], qf, kh+2);
    }
}
// PV s-block: 8 V ldsm + 16 MMAs
__device__ __forceinline__ void pv_s(float oacc[16][4], const uint32_t* pF, uint32_t vb_, int s)
{
    #pragma unroll
    for (int u = 0; u < 8; u++) {
        uint32_t vh[4];
        ldsm4(vh, vb_ + (uint32_t)u * 2304 + (uint32_t)s * 32);
        mma16816(oacc[2*u],   pF, vh);   mma16816(oacc[2*u+1], pF, vh+2);
    }
}

// ---- softmax half: nt in [4h, 4h+4) -> pF[8h..8h+8), l accumulation ----
__device__ __forceinline__ void softmax_half(const float sacc[8][4], uint32_t* pF,
                                             float& l0, float& l1, int n0, int r0,
                                             bool causal, int lane, int h)
{
    const bool needmask = causal && (n0 + BN - 1 > r0);
    #pragma unroll
    for (int nt = 4 * h; nt < 4 * h + 4; nt++) {
        float p0 = ex2f(sacc[nt][0]);
        float p1 = ex2f(sacc[nt][1]);
        float p2 = ex2f(sacc[nt][2]);
        float p3 = ex2f(sacc[nt][3]);
        if (needmask) {
            int c0 = n0 + 8 * nt + 2 * (lane & 3);
            if (c0 > r0) p0 = 0.0f;
            if (c0 + 1 > r0) p1 = 0.0f;
            if (c0 > r0 + 8) p2 = 0.0f;
            if (c0 + 1 > r0 + 8) p3 = 0.0f;
        }
        l0 += p0 + p1;
        l1 += p2 + p3;
        pF[2*nt]   = pack_h2(p0, p1);
        pF[2*nt+1] = pack_h2(p2, p3);
    }
}

__global__ void __launch_bounds__(NT, 2)
fa_hmma11(const float* __restrict__ Q, const int* __restrict__ causal_flag,
          float* __restrict__ O, int S, int H)
{
    extern __shared__ char smem[];
    const uint32_t sb = smem_u32(smem);
    const int tid  = threadIdx.x;
    const int lane = tid & 31;
    const int wid  = tid >> 5;                      // 0..3
    const int qi = gridDim.x - 1 - blockIdx.x;      // longest CTAs first
    const int h = blockIdx.y, b = blockIdx.z;
    const int q0 = qi * BM;
    const int rs = H * DH;
    const bool causal = (causal_flag[0] != 0);
    const int ntiles = causal ? (qi + 1) : (S / BN);

    const uint32_t swz = lane & 7;
    const uint32_t hiA = (uint32_t)lane >> 4;
    const uint32_t kh8 = ((uint32_t)lane >> 3) & 1;
    const uint32_t rowA = (uint32_t)wid * 16 + (lane & 15);
    const uint32_t bnl = 8 * hiA + swz;
    const uint32_t qoffH = sb + QH_OFF + rowA * 256;
    const int r0 = q0 + wid * 16 + (lane >> 2);

    const char* kvbase = g_kv + ((size_t)((b * HCONST + h) * NKV)) * BUFSZ;

    // ---- issue tile0 + tile1 image copies ----
    copy_img<BUFSZ>(sb + BUF0, kvbase, tid);
    CP_COMMIT();
    copy_img<BUFSZ>(sb + BUF0 + BUFSZ, kvbase + BUFSZ, tid);
    CP_COMMIT();

    // ---- convert Q tile to fp16 (scale*log2e folded), overlaps copies ----
    {
        const float* qg = Q + ((size_t)(b * S + q0)) * rs + (size_t)h * DH;
        #pragma unroll
        for (int it = 0; it < 16; it++) {
            int idx = tid + NT * it;                 // 0..2047
            int r = idx >> 5, c4 = idx & 31;
            float4 v = *(const float4*)(qg + (size_t)r * rs + c4 * 4);
            uint32_t w0 = pack_h2(v.x * SCALE2, v.y * SCALE2);
            uint32_t w1 = pack_h2(v.z * SCALE2, v.w * SCALE2);
            uint32_t o = (uint32_t)r * 256 + ((((uint32_t)(c4 >> 1)) ^ (r & 7)) << 4) + (c4 & 1) * 8;
            *(uint2*)(smem + QH_OFF + o) = make_uint2(w0, w1);
        }
    }
    __syncthreads();   // Q smem complete for all warps

    // ---- load Q fragments into registers ONCE (tile-invariant) ----
    uint32_t qF[32];
    #pragma unroll
    for (int ks = 0; ks < 8; ks++)
        ldsm4(qF + 4 * ks, qoffH + (((((uint32_t)ks << 1) | hiA) ^ swz) << 4));

    CP_WAIT0();
    __syncthreads();

    float oacc[16][4];
    #pragma unroll
    for (int t = 0; t < 16; t++)
        #pragma unroll
        for (int e = 0; e < 4; e++) oacc[t][e] = 0.0f;
    float l0 = 0.0f, l1 = 0.0f;
    uint32_t pF[16];
    float sacc[8][4];
    #pragma unroll
    for (int t = 0; t < 8; t++)
        #pragma unroll
        for (int e = 0; e < 4; e++) sacc[t][e] = 0.0f;

    // ---- prologue: QK(0) ----
    {
        const uint32_t kb_ = sb + BUF0 + KH_O + bnl * 256;   // buf0
        #pragma unroll
        for (int ks = 0; ks < 8; ks++)
            qk_ks(sacc, qF + 4 * ks, kb_, ks, swz, kh8);
    }
    __syncthreads();   // all warps done with buf0.K before K(2) copy overwrites it

    // ---- main loop: iter j does softmax(j), then PV(j) || QK(j+1) ----
    for (int j = 0; j < ntiles - 1; j++) {
        const uint32_t vbuf = sb + BUF0 + (uint32_t)(j & 1) * BUFSZ;        // V(j); K(j+2)/V(j+2) dst
        const uint32_t kbuf = sb + BUF0 + (uint32_t)((j + 1) & 1) * BUFSZ;  // K(j+1)
        const uint32_t kb_ = kbuf + KH_O + bnl * 256;
        const uint32_t vb_ = vbuf + VTH_O + bnl * 144 + kh8 * 16;
        const bool more2 = (j + 2 < ntiles);
        const char* g2 = kvbase + (size_t)(j + 2) * BUFSZ;
        const int n0 = j * BN;

        // K(j+2) -> buf[j&1].K  (K(j) consumed by all warps last iteration; barrier passed)
        if (more2)
            copy_img<KREG_BYTES>(vbuf + KH_O, g2 + KH_O, tid);
        CP_COMMIT();

        // softmax(j): consumes sacc, fills pF; sacc reused for QK(j+1)
        softmax_half(sacc, pF, l0, l1, n0, r0, causal, lane, 0);
        softmax_half(sacc, pF, l0, l1, n0, r0, causal, lane, 1);
        #pragma unroll
        for (int t = 0; t < 8; t++)
            #pragma unroll
            for (int e = 0; e < 4; e++) sacc[t][e] = 0.0f;

        qk_ks(sacc, qF + 0,  kb_, 0, swz, kh8);  pv_s(oacc, pF + 0,  vb_, 0);
        qk_ks(sacc, qF + 4,  kb_, 1, swz, kh8);  pv_s(oacc, pF + 4,  vb_, 1);
        qk_ks(sacc, qF + 8,  kb_, 2, swz, kh8);  pv_s(oacc, pF + 8,  vb_, 2);
        qk_ks(sacc, qF + 12, kb_, 3, swz, kh8);  pv_s(oacc, pF + 12, vb_, 3);

        // === WAR fence: ALL warps must finish reading V(j) before V(j+2) stores issue ===
        __syncthreads();

        // V(j+2) -> buf[j&1].V (now quiescent)
        if (more2)
            copy_img<VREG_BYTES>(vbuf + VTH_O, g2 + VTH_O, tid);
        CP_COMMIT();

        qk_ks(sacc, qF + 16, kb_, 4, swz, kh8);
        qk_ks(sacc, qF + 20, kb_, 5, swz, kh8);
        qk_ks(sacc, qF + 24, kb_, 6, swz, kh8);
        qk_ks(sacc, qF + 28, kb_, 7, swz, kh8);

        CP_WAIT1();        // K(j+2) landed; V(j+2) may still fly (needed next-next iter)
        __syncthreads();
    }

    // ---- tail: softmax + PV of tile (ntiles-1) ----
    {
        const uint32_t vbuf = sb + BUF0 + (uint32_t)((ntiles - 1) & 1) * BUFSZ;
        const uint32_t vb_ = vbuf + VTH_O + bnl * 144 + kh8 * 16;
        const int n0 = (ntiles - 1) * BN;
        softmax_half(sacc, pF, l0, l1, n0, r0, causal, lane, 0);
        softmax_half(sacc, pF, l0, l1, n0, r0, causal, lane, 1);
        pv_s(oacc, pF + 0, vb_, 0);
        pv_s(oacc, pF + 4, vb_, 1);
        pv_s(oacc, pF + 8,  vb_, 2);
        pv_s(oacc, pF + 12, vb_, 3);
    }

    // ---- epilogue ----
    l0 += __shfl_xor_sync(0xffffffffu, l0, 1);
    l0 += __shfl_xor_sync(0xffffffffu, l0, 2);
    l1 += __shfl_xor_sync(0xffffffffu, l1, 1);
    l1 += __shfl_xor_sync(0xffffffffu, l1, 2);
    const float i0 = 1.0f / l0, i1 = 1.0f / l1;

    float* o0 = O + ((size_t)(b * S + r0)) * rs + (size_t)h * DH;
    float* o1 = O + ((size_t)(b * S + r0 + 8)) * rs + (size_t)h * DH;
    const int cofs = 2 * (lane & 3);
    #pragma unroll
    for (int t = 0; t < 16; t++) {
        *(float2*)(o0 + 8 * t + cofs) = make_float2(oacc[t][0] * i0, oacc[t][1] * i0);
        *(float2*)(o1 + 8 * t + cofs) = make_float2(oacc[t][2] * i1, oacc[t][3] * i1);
    }
}

extern "C" void kernel_launch(void* const* d_in, const int* in_sizes, int n_in,
                              void* d_out, int out_size) {
    const float* q = (const float*)d_in[0];
    const float* k = (const float*)d_in[1];
    const float* v = (const float*)d_in[2];
    const int* causal = (const int*)d_in[3];
    float* out = (float*)d_out;

    const int B = 2, H = 16, D = 128;
    const int S = in_sizes[0] / (B * H * D);   // 2048

    dim3 pgrid(S / BN, H, B);
    kv_prepass<<<pgrid, PNT>>>(k, v, S, H);

    cudaFuncSetAttribute(fa_hmma11, cudaFuncAttributeMaxDynamicSharedMemorySize, SMEM_TOTAL);
    dim3 grid(S / BM, H, B);
    fa_hmma11<<<grid, NT, SMEM_TOTAL>>>(q, causal, out, S, H);
}

// round 15
// speedup vs baseline: 1.1349x; 1.0156x over previous
#include <cuda_runtime.h>
#include <cuda_fp16.h>
#include <cstdint>

#define NT 128
#define BM 64
#define BN 64
#define DH 128
#define HCONST 16
#define NKV 32            // S/BN for S=2048

// ---- gmem tile-image layout (per tile) ----
#define KH_O 0                   // K fp16: 64 x 256B (swizzled)      16384 B
#define VTH_O 16384              // V^T fp16: 128 d-rows x 144B       18432 B
#define IMGSZ 34816
#define KSZ 16384
#define VSZ 18432

// ---- SMEM byte layout (main kernel) ----
#define QH_OFF 0                 // Q fp16: 64 rows x 256B (swizzled)
#define KBUF0  16384             // K double buffer: 2 x 16384
#define VBUF0  49152             // V triple buffer: 3 x 18432
#define SMEM_TOTAL 104448        // 16K + 32K + 55.3K -> 2 CTAs/SM

// 1/sqrt(128) * log2(e)
#define SCALE2 0.1275200917303861f

// Precomputed KV tile images: [B][H][NKV] x IMGSZ bytes
__device__ __align__(128) char g_kv[2 * HCONST * NKV * (size_t)IMGSZ];

__device__ __forceinline__ uint32_t smem_u32(const void* p) {
    uint32_t a;
    asm("{ .reg .u64 t; cvta.to.shared.u64 t, %1; cvt.u32.u64 %0, t; }" : "=r"(a) : "l"(p));
    return a;
}
__device__ __forceinline__ void ldsm4(uint32_t r[4], uint32_t addr) {
    asm volatile("ldmatrix.sync.aligned.m8n8.x4.shared.b16 {%0,%1,%2,%3}, [%4];"
                 : "=r"(r[0]), "=r"(r[1]), "=r"(r[2]), "=r"(r[3]) : "r"(addr));
}
__device__ __forceinline__ void mma16816(float c[4], const uint32_t a[4], const uint32_t b[2]) {
    asm volatile("mma.sync.aligned.m16n8k16.row.col.f32.f16.f16.f32 "
                 "{%0,%1,%2,%3}, {%4,%5,%6,%7}, {%8,%9}, {%0,%1,%2,%3};"
                 : "+f"(c[0]), "+f"(c[1]), "+f"(c[2]), "+f"(c[3])
                 : "r"(a[0]), "r"(a[1]), "r"(a[2]), "r"(a[3]), "r"(b[0]), "r"(b[1]));
}
__device__ __forceinline__ float ex2f(float x) {
    float y; asm("ex2.approx.f32 %0, %1;" : "=f"(y) : "f"(x)); return y;
}
__device__ __forceinline__ void cp16(uint32_t saddr, const char* g) {
    asm volatile("cp.async.cg.shared.global [%0], [%1], 16;" :: "r"(saddr), "l"(g));
}
#define CP_COMMIT() asm volatile("cp.async.commit_group;" ::: "memory")
#define CP_WAIT0()  asm volatile("cp.async.wait_group 0;" ::: "memory")
#define CP_WAIT1()  asm volatile("cp.async.wait_group 1;" ::: "memory")

// Copy BYTES from gmem image to smem (NT*16 = 2048 per sweep; half-sweep tail ok).
template <int BYTES>
__device__ __forceinline__ void copy_img(uint32_t sdst, const char* g, int tid) {
    #pragma unroll
    for (int o = 0; o + NT * 16 <= BYTES; o += NT * 16)
        cp16(sdst + o + tid * 16, g + o + tid * 16);
    if constexpr (BYTES % (NT * 16) != 0) {
        constexpr int o = (BYTES / (NT * 16)) * (NT * 16);
        if (tid < (BYTES - o) / 16)
            cp16(sdst + o + tid * 16, g + o + tid * 16);
    }
}

__device__ __forceinline__ uint32_t pack_h2(float x, float y) {
    __half2 v = __floats2half2_rn(x, y);
    return *(uint32_t*)&v;
}

// ================= prepass: build tile image in SMEM, stream out coalesced =================
#define PNT 256
__global__ void __launch_bounds__(PNT, 4)
kv_prepass(const float* __restrict__ K, const float* __restrict__ V, int S, int H)
{
    __shared__ __align__(16) char simg[IMGSZ];
    const int t = blockIdx.x, h = blockIdx.y, b = blockIdx.z;
    const int tid = threadIdx.x;
    const int rs = H * DH;
    char* img = g_kv + ((size_t)((b * HCONST + h) * NKV + t)) * IMGSZ;
    const float* kg = K + ((size_t)(b * S + t * BN)) * rs + (size_t)h * DH;
    const float* vg = V + ((size_t)(b * S + t * BN)) * rs + (size_t)h * DH;
    // K: scattered swizzle stores into smem
    #pragma unroll
    for (int it = 0; it < 8; it++) {
        int idx = tid + PNT * it;                // 0..2047
        int r = idx >> 5, c4 = idx & 31;
        float4 v = *(const float4*)(kg + (size_t)r * rs + c4 * 4);
        uint32_t w0 = pack_h2(v.x, v.y);
        uint32_t w1 = pack_h2(v.z, v.w);
        uint32_t o = (uint32_t)r * 256 + ((((uint32_t)(c4 >> 1)) ^ (r & 7)) << 4) + (c4 & 1) * 8;
        *(uint2*)(simg + KH_O + o) = make_uint2(w0, w1);
    }
    // V^T: scattered stride-144 stores into smem
    #pragma unroll
    for (int it = 0; it < 4; it++) {
        int idx = tid + PNT * it;                // 0..1023
        int a = idx & 31, dc = idx >> 5;
        float4 v0 = *(const float4*)(vg + (size_t)(2 * a) * rs + dc * 4);
        float4 v1 = *(const float4*)(vg + (size_t)(2 * a + 1) * rs + dc * 4);
        const float* e0 = (const float*)&v0;
        const float* e1 = (const float*)&v1;
        #pragma unroll
        for (int i = 0; i < 4; i++) {
            uint32_t w = pack_h2(e0[i], e1[i]);
            uint32_t o = (uint32_t)(dc * 4 + i) * 144 + a * 4;
            *(uint32_t*)(simg + VTH_O + o) = w;
        }
    }
    __syncthreads();
    // stream out fully coalesced (16B per thread per sweep)
    #pragma unroll
    for (int o = 0; o + PNT * 16 <= IMGSZ; o += PNT * 16)
        *(uint4*)(img + o + tid * 16) = *(const uint4*)(simg + o + tid * 16);
    {
        constexpr int o = (IMGSZ / (PNT * 16)) * (PNT * 16);   // 32768; tail 2048B
        if (tid < (IMGSZ - o) / 16)
            *(uint4*)(img + o + tid * 16) = *(const uint4*)(simg + o + tid * 16);
    }
}

// ---- MMA sub-blocks ----
// QK ks-block: Q from registers (qF), 4 K ldsm + 8 MMAs
__device__ __forceinline__ void qk_ks(float sacc[8][4], const uint32_t* qf, uint32_t kb_,
                                      int ks, uint32_t swz, uint32_t kh8)
{
    const uint32_t kch = (((((uint32_t)ks << 1) | kh8) ^ swz) << 4);
    #pragma unroll
    for (int t = 0; t < 4; t++) {
        uint32_t kh[4];
        ldsm4(kh, kb_ + (uint32_t)t * 4096 + kch);
        mma16816(sacc[2*t],   qf, kh);   mma16816(sacc[2*t+1], qf, kh+2);
    }
}
// PV s-block: 8 V ldsm + 16 MMAs
__device__ __forceinline__ void pv_s(float oacc[16][4], const uint32_t* pF, uint32_t vb_, int s)
{
    #pragma unroll
    for (int u = 0; u < 8; u++) {
        uint32_t vh[4];
        ldsm4(vh, vb_ + (uint32_t)u * 2304 + (uint32_t)s * 32);
        mma16816(oacc[2*u],   pF, vh);   mma16816(oacc[2*u+1], pF, vh+2);
    }
}

// ---- softmax half: nt in [4h, 4h+4) -> pF[8h..8h+8), l accumulation ----
__device__ __forceinline__ void softmax_half(const float sacc[8][4], uint32_t* pF,
                                             float& l0, float& l1, int n0, int r0,
                                             bool causal, int lane, int h)
{
    const bool needmask = causal && (n0 + BN - 1 > r0);
    #pragma unroll
    for (int nt = 4 * h; nt < 4 * h + 4; nt++) {
        float p0 = ex2f(sacc[nt][0]);
        float p1 = ex2f(sacc[nt][1]);
        float p2 = ex2f(sacc[nt][2]);
        float p3 = ex2f(sacc[nt][3]);
        if (needmask) {
            int c0 = n0 + 8 * nt + 2 * (lane & 3);
            if (c0 > r0) p0 = 0.0f;
            if (c0 + 1 > r0) p1 = 0.0f;
            if (c0 > r0 + 8) p2 = 0.0f;
            if (c0 + 1 > r0 + 8) p3 = 0.0f;
        }
        l0 += p0 + p1;
        l1 += p2 + p3;
        pF[2*nt]   = pack_h2(p0, p1);
        pF[2*nt+1] = pack_h2(p2, p3);
    }
}

__global__ void __launch_bounds__(NT, 2)
fa_hmma12(const float* __restrict__ Q, const int* __restrict__ causal_flag,
          float* __restrict__ O, int S, int H)
{
    extern __shared__ char smem[];
    const uint32_t sb = smem_u32(smem);
    const int tid  = threadIdx.x;
    const int lane = tid & 31;
    const int wid  = tid >> 5;                      // 0..3
    const int qi = gridDim.x - 1 - blockIdx.x;      // longest CTAs first
    const int h = blockIdx.y, b = blockIdx.z;
    const int q0 = qi * BM;
    const int rs = H * DH;
    const bool causal = (causal_flag[0] != 0);
    const int ntiles = causal ? (qi + 1) : (S / BN);

    const uint32_t swz = lane & 7;
    const uint32_t hiA = (uint32_t)lane >> 4;
    const uint32_t kh8 = ((uint32_t)lane >> 3) & 1;
    const uint32_t rowA = (uint32_t)wid * 16 + (lane & 15);
    const uint32_t bnl = 8 * hiA + swz;
    const uint32_t qoffH = sb + QH_OFF + rowA * 256;
    const int r0 = q0 + wid * 16 + (lane >> 2);

    const char* kvbase = g_kv + ((size_t)((b * HCONST + h) * NKV)) * IMGSZ;

    // ---- issue K0,V0 + K1,V1 copies ----
    copy_img<KSZ>(sb + KBUF0, kvbase + KH_O, tid);
    copy_img<VSZ>(sb + VBUF0, kvbase + VTH_O, tid);
    CP_COMMIT();
    copy_img<KSZ>(sb + KBUF0 + KSZ, kvbase + IMGSZ + KH_O, tid);
    copy_img<VSZ>(sb + VBUF0 + VSZ, kvbase + IMGSZ + VTH_O, tid);
    CP_COMMIT();

    // ---- convert Q tile to fp16 (scale*log2e folded), overlaps copies ----
    {
        const float* qg = Q + ((size_t)(b * S + q0)) * rs + (size_t)h * DH;
        #pragma unroll
        for (int it = 0; it < 16; it++) {
            int idx = tid + NT * it;                 // 0..2047
            int r = idx >> 5, c4 = idx & 31;
            float4 v = *(const float4*)(qg + (size_t)r * rs + c4 * 4);
            uint32_t w0 = pack_h2(v.x * SCALE2, v.y * SCALE2);
            uint32_t w1 = pack_h2(v.z * SCALE2, v.w * SCALE2);
            uint32_t o = (uint32_t)r * 256 + ((((uint32_t)(c4 >> 1)) ^ (r & 7)) << 4) + (c4 & 1) * 8;
            *(uint2*)(smem + QH_OFF + o) = make_uint2(w0, w1);
        }
    }
    __syncthreads();   // Q smem complete for all warps

    // ---- load Q fragments into registers ONCE (tile-invariant) ----
    uint32_t qF[32];
    #pragma unroll
    for (int ks = 0; ks < 8; ks++)
        ldsm4(qF + 4 * ks, qoffH + (((((uint32_t)ks << 1) | hiA) ^ swz) << 4));

    CP_WAIT0();
    __syncthreads();

    float oacc[16][4];
    #pragma unroll
    for (int t = 0; t < 16; t++)
        #pragma unroll
        for (int e = 0; e < 4; e++) oacc[t][e] = 0.0f;
    float l0 = 0.0f, l1 = 0.0f;
    uint32_t pF[16];
    float sacc[8][4];
    #pragma unroll
    for (int t = 0; t < 8; t++)
        #pragma unroll
        for (int e = 0; e < 4; e++) sacc[t][e] = 0.0f;

    // ---- prologue: QK(0) ----
    {
        const uint32_t kb_ = sb + KBUF0 + bnl * 256;   // K buf 0
        #pragma unroll
        for (int ks = 0; ks < 8; ks++)
            qk_ks(sacc, qF + 4 * ks, kb_, ks, swz, kh8);
    }
    __syncthreads();   // all warps done with Kbuf0 before K(2) copy overwrites it

    // ---- main loop: single barrier per tile; K double, V triple buffered ----
    // iter j: issue K(j+2)->Kbuf[j&1], V(j+2)->Vbuf[(j+2)%3]; softmax(j); QK(j+1)||PV(j)
    int vm0 = 0, vm1 = 1, vm2 = 2;   // Vbuf indices of tiles j, j+1, j+2
    for (int j = 0; j < ntiles - 1; j++) {
        const uint32_t kb_ = sb + KBUF0 + (uint32_t)((j + 1) & 1) * KSZ + bnl * 256;  // K(j+1)
        const uint32_t vb_ = sb + VBUF0 + (uint32_t)vm0 * VSZ + bnl * 144 + kh8 * 16; // V(j)
        const bool more2 = (j + 2 < ntiles);
        const char* g2 = kvbase + (size_t)(j + 2) * IMGSZ;
        const int n0 = j * BN;

        // K(j+2) -> Kbuf[j&1] (K(j) reads finished last iter, barrier passed)
        if (more2)
            copy_img<KSZ>(sb + KBUF0 + (uint32_t)(j & 1) * KSZ, g2 + KH_O, tid);
        CP_COMMIT();
        // V(j+2) -> Vbuf[vm2] (V(j-1) reads finished last iter; vm2 untouched this iter)
        if (more2)
            copy_img<VSZ>(sb + VBUF0 + (uint32_t)vm2 * VSZ, g2 + VTH_O, tid);
        CP_COMMIT();

        // softmax(j): consumes sacc, fills pF; sacc reused for QK(j+1)
        softmax_half(sacc, pF, l0, l1, n0, r0, causal, lane, 0);
        softmax_half(sacc, pF, l0, l1, n0, r0, causal, lane, 1);
        #pragma unroll
        for (int t = 0; t < 8; t++)
            #pragma unroll
            for (int e = 0; e < 4; e++) sacc[t][e] = 0.0f;

        qk_ks(sacc, qF + 0,  kb_, 0, swz, kh8);  pv_s(oacc, pF + 0,  vb_, 0);
        qk_ks(sacc, qF + 4,  kb_, 1, swz, kh8);  pv_s(oacc, pF + 4,  vb_, 1);
        qk_ks(sacc, qF + 8,  kb_, 2, swz, kh8);  pv_s(oacc, pF + 8,  vb_, 2);
        qk_ks(sacc, qF + 12, kb_, 3, swz, kh8);  pv_s(oacc, pF + 12, vb_, 3);
        qk_ks(sacc, qF + 16, kb_, 4, swz, kh8);
        qk_ks(sacc, qF + 20, kb_, 5, swz, kh8);
        qk_ks(sacc, qF + 24, kb_, 6, swz, kh8);
        qk_ks(sacc, qF + 28, kb_, 7, swz, kh8);

        int tmp = vm0; vm0 = vm1; vm1 = vm2; vm2 = tmp;

        CP_WAIT1();        // K(j+2) group landed (V(j+2) group may still fly)
        __syncthreads();   // single barrier per tile
    }

    // ---- tail: softmax + PV of tile (ntiles-1); V copy group may be in flight ----
    {
        CP_WAIT0();        // ensure V(ntiles-1) landed (no-op if already)
        const uint32_t vb_ = sb + VBUF0 + (uint32_t)vm0 * VSZ + bnl * 144 + kh8 * 16;
        const int n0 = (ntiles - 1) * BN;
        softmax_half(sacc, pF, l0, l1, n0, r0, causal, lane, 0);
        softmax_half(sacc, pF, l0, l1, n0, r0, causal, lane, 1);
        pv_s(oacc, pF + 0, vb_, 0);
        pv_s(oacc, pF + 4, vb_, 1);
        pv_s(oacc, pF + 8,  vb_, 2);
        pv_s(oacc, pF + 12, vb_, 3);
    }

    // ---- epilogue ----
    l0 += __shfl_xor_sync(0xffffffffu, l0, 1);
    l0 += __shfl_xor_sync(0xffffffffu, l0, 2);
    l1 += __shfl_xor_sync(0xffffffffu, l1, 1);
    l1 += __shfl_xor_sync(0xffffffffu, l1, 2);
    const float i0 = 1.0f / l0, i1 = 1.0f / l1;

    float* o0 = O + ((size_t)(b * S + r0)) * rs + (size_t)h * DH;
    float* o1 = O + ((size_t)(b * S + r0 + 8)) * rs + (size_t)h * DH;
    const int cofs = 2 * (lane & 3);
    #pragma unroll
    for (int t = 0; t < 16; t++) {
        *(float2*)(o0 + 8 * t + cofs) = make_float2(oacc[t][0] * i0, oacc[t][1] * i0);
        *(float2*)(o1 + 8 * t + cofs) = make_float2(oacc[t][2] * i1, oacc[t][3] * i1);
    }
}

extern "C" void kernel_launch(void* const* d_in, const int* in_sizes, int n_in,
                              void* d_out, int out_size) {
    const float* q = (const float*)d_in[0];
    const float* k = (const float*)d_in[1];
    const float* v = (const float*)d_in[2];
    const int* causal = (const int*)d_in[3];
    float* out = (float*)d_out;

    const int B = 2, H = 16, D = 128;
    const int S = in_sizes[0] / (B * H * D);   // 2048

    dim3 pgrid(S / BN, H, B);
    kv_prepass<<<pgrid, PNT>>>(k, v, S, H);

    cudaFuncSetAttribute(fa_hmma12, cudaFuncAttributeMaxDynamicSharedMemorySize, SMEM_TOTAL);
    dim3 grid(S / BM, H, B);
    fa_hmma12<<<grid, NT, SMEM_TOTAL>>>(q, causal, out, S, H);
}

// round 16
// speedup vs baseline: 1.1897x; 1.0482x over previous
#include <cuda_runtime.h>
#include <cuda_fp16.h>
#include <cstdint>

#define NT 128
#define BM 64
#define BN 32
#define DH 128
#define HCONST 16
#define NKV 64            // S/BN for S=2048

// ---- gmem tile-image layout (per 32-row tile) ----
#define KH_O 0                   // K fp16: 32 x 256B (swizzled)      8192 B
#define VTH_O 8192               // V^T fp16: 128 d-rows x 80B        10240 B
#define IMGSZ 18432
#define KSZ 8192
#define VSZ 10240

// ---- SMEM byte layout (main kernel) ----
#define QH_OFF 0                 // Q fp16: 64 rows x 256B (swizzled)
#define KBUF0  16384             // K double buffer: 2 x 8192
#define VBUF0  32768             // V triple buffer: 3 x 10240
#define SMEM_TOTAL 63488         // -> 3 CTAs/SM (190.5 KB)

// 1/sqrt(128) * log2(e)
#define SCALE2 0.1275200917303861f

// Precomputed KV tile images: [B][H][NKV] x IMGSZ bytes
__device__ __align__(128) char g_kv[2 * HCONST * NKV * (size_t)IMGSZ];

__device__ __forceinline__ uint32_t smem_u32(const void* p) {
    uint32_t a;
    asm("{ .reg .u64 t; cvta.to.shared.u64 t, %1; cvt.u32.u64 %0, t; }" : "=r"(a) : "l"(p));
    return a;
}
__device__ __forceinline__ void ldsm4(uint32_t r[4], uint32_t addr) {
    asm volatile("ldmatrix.sync.aligned.m8n8.x4.shared.b16 {%0,%1,%2,%3}, [%4];"
                 : "=r"(r[0]), "=r"(r[1]), "=r"(r[2]), "=r"(r[3]) : "r"(addr));
}
__device__ __forceinline__ void mma16816(float c[4], const uint32_t a[4], const uint32_t b[2]) {
    asm volatile("mma.sync.aligned.m16n8k16.row.col.f32.f16.f16.f32 "
                 "{%0,%1,%2,%3}, {%4,%5,%6,%7}, {%8,%9}, {%0,%1,%2,%3};"
                 : "+f"(c[0]), "+f"(c[1]), "+f"(c[2]), "+f"(c[3])
                 : "r"(a[0]), "r"(a[1]), "r"(a[2]), "r"(a[3]), "r"(b[0]), "r"(b[1]));
}
// zero-accumulate variant: d = a*b + 0 (ptxas uses RZ; kills sacc re-zero MOVs)
__device__ __forceinline__ void mma16816_z(float d[4], const uint32_t a[4], const uint32_t b[2]) {
    asm volatile("mma.sync.aligned.m16n8k16.row.col.f32.f16.f16.f32 "
                 "{%0,%1,%2,%3}, {%4,%5,%6,%7}, {%8,%9}, {%10,%11,%12,%13};"
                 : "=f"(d[0]), "=f"(d[1]), "=f"(d[2]), "=f"(d[3])
                 : "r"(a[0]), "r"(a[1]), "r"(a[2]), "r"(a[3]), "r"(b[0]), "r"(b[1]),
                   "f"(0.0f), "f"(0.0f), "f"(0.0f), "f"(0.0f));
}
__device__ __forceinline__ float ex2f(float x) {
    float y; asm("ex2.approx.f32 %0, %1;" : "=f"(y) : "f"(x)); return y;
}
__device__ __forceinline__ void cp16(uint32_t saddr, const char* g) {
    asm volatile("cp.async.cg.shared.global [%0], [%1], 16;" :: "r"(saddr), "l"(g));
}
#define CP_COMMIT() asm volatile("cp.async.commit_group;" ::: "memory")
#define CP_WAIT0()  asm volatile("cp.async.wait_group 0;" ::: "memory")
#define CP_WAIT1()  asm volatile("cp.async.wait_group 1;" ::: "memory")

// Copy BYTES (multiple of NT*16 = 2048) from gmem image to smem.
template <int BYTES>
__device__ __forceinline__ void copy_img(uint32_t sdst, const char* g, int tid) {
    #pragma unroll
    for (int o = 0; o < BYTES; o += NT * 16)
        cp16(sdst + o + tid * 16, g + o + tid * 16);
}

__device__ __forceinline__ uint32_t pack_h2(float x, float y) {
    __half2 v = __floats2half2_rn(x, y);
    return *(uint32_t*)&v;
}

// ================= prepass: K,V fp32 -> fp16 tile images (direct stores) =================
#define PNT 256
__global__ void __launch_bounds__(PNT, 4)
kv_prepass(const float* __restrict__ K, const float* __restrict__ V, int S, int H)
{
    const int t = blockIdx.x, h = blockIdx.y, b = blockIdx.z;
    const int tid = threadIdx.x;
    const int rs = H * DH;
    char* img = g_kv + ((size_t)((b * HCONST + h) * NKV + t)) * IMGSZ;
    const float* kg = K + ((size_t)(b * S + t * BN)) * rs + (size_t)h * DH;
    const float* vg = V + ((size_t)(b * S + t * BN)) * rs + (size_t)h * DH;
    // K: 32 rows x 128 cols fp32 -> swizzled fp16 (1024 float4 items)
    #pragma unroll
    for (int it = 0; it < 4; it++) {
        int idx = tid + PNT * it;                // 0..1023
        int r = idx >> 5, c4 = idx & 31;
        float4 v = *(const float4*)(kg + (size_t)r * rs + c4 * 4);
        uint32_t w0 = pack_h2(v.x, v.y);
        uint32_t w1 = pack_h2(v.z, v.w);
        uint32_t o = (uint32_t)r * 256 + ((((uint32_t)(c4 >> 1)) ^ (r & 7)) << 4) + (c4 & 1) * 8;
        *(uint2*)(img + KH_O + o) = make_uint2(w0, w1);
    }
    // V^T: 128 d-rows x 32 n (80B rows); 512 items (a=n-pair 0..15, dc=d-chunk 0..31)
    #pragma unroll
    for (int it = 0; it < 2; it++) {
        int idx = tid + PNT * it;                // 0..511
        int a = idx & 15, dc = idx >> 4;
        float4 v0 = *(const float4*)(vg + (size_t)(2 * a) * rs + dc * 4);
        float4 v1 = *(const float4*)(vg + (size_t)(2 * a + 1) * rs + dc * 4);
        const float* e0 = (const float*)&v0;
        const float* e1 = (const float*)&v1;
        #pragma unroll
        for (int i = 0; i < 4; i++) {
            uint32_t w = pack_h2(e0[i], e1[i]);
            uint32_t o = (uint32_t)(dc * 4 + i) * 80 + a * 4;
            *(uint32_t*)(img + VTH_O + o) = w;
        }
    }
}

// ---- MMA sub-blocks (BN=32) ----
// QK ks-block: Q from registers (qF), 2 K ldsm + 4 MMAs. Z=true -> zero-accumulate.
template <bool Z>
__device__ __forceinline__ void qk_ks(float sacc[4][4], const uint32_t* qf, uint32_t kb_,
                                      int ks, uint32_t swz, uint32_t kh8)
{
    const uint32_t kch = (((((uint32_t)ks << 1) | kh8) ^ swz) << 4);
    #pragma unroll
    for (int t = 0; t < 2; t++) {
        uint32_t kh[4];
        ldsm4(kh, kb_ + (uint32_t)t * 4096 + kch);
        if (Z) { mma16816_z(sacc[2*t], qf, kh);  mma16816_z(sacc[2*t+1], qf, kh+2); }
        else   { mma16816(sacc[2*t],   qf, kh);  mma16816(sacc[2*t+1],   qf, kh+2); }
    }
}
// PV s-block: 8 V ldsm + 16 MMAs (s in {0,1}: 16-n k-slice)
__device__ __forceinline__ void pv_s(float oacc[16][4], const uint32_t* pF, uint32_t vb_, int s)
{
    #pragma unroll
    for (int u = 0; u < 8; u++) {
        uint32_t vh[4];
        ldsm4(vh, vb_ + (uint32_t)u * 1280 + (uint32_t)s * 32);
        mma16816(oacc[2*u],   pF, vh);   mma16816(oacc[2*u+1], pF, vh+2);
    }
}

// ---- softmax tile (4 frags) -> pF[8], l accumulation ----
__device__ __forceinline__ void softmax_tile(const float sacc[4][4], uint32_t* pF,
                                             float& l0, float& l1, int n0, int r0,
                                             bool causal, int lane)
{
    const bool needmask = causal && (n0 + BN - 1 > r0);
    #pragma unroll
    for (int nt = 0; nt < 4; nt++) {
        float p0 = ex2f(sacc[nt][0]);
        float p1 = ex2f(sacc[nt][1]);
        float p2 = ex2f(sacc[nt][2]);
        float p3 = ex2f(sacc[nt][3]);
        if (needmask) {
            int c0 = n0 + 8 * nt + 2 * (lane & 3);
            if (c0 > r0) p0 = 0.0f;
            if (c0 + 1 > r0) p1 = 0.0f;
            if (c0 > r0 + 8) p2 = 0.0f;
            if (c0 + 1 > r0 + 8) p3 = 0.0f;
        }
        l0 += p0 + p1;
        l1 += p2 + p3;
        pF[2*nt]   = pack_h2(p0, p1);
        pF[2*nt+1] = pack_h2(p2, p3);
    }
}

__global__ void __launch_bounds__(NT, 3)
fa_hmma13(const float* __restrict__ Q, const int* __restrict__ causal_flag,
          float* __restrict__ O, int S, int H)
{
    extern __shared__ char smem[];
    const uint32_t sb = smem_u32(smem);
    const int tid  = threadIdx.x;
    const int lane = tid & 31;
    const int wid  = tid >> 5;                      // 0..3
    const int qi = gridDim.x - 1 - blockIdx.x;      // longest CTAs first
    const int h = blockIdx.y, b = blockIdx.z;
    const int q0 = qi * BM;
    const int rs = H * DH;
    const bool causal = (causal_flag[0] != 0);
    const int ntiles = causal ? 2 * (qi + 1) : (S / BN);

    const uint32_t swz = lane & 7;
    const uint32_t hiA = (uint32_t)lane >> 4;
    const uint32_t kh8 = ((uint32_t)lane >> 3) & 1;
    const uint32_t rowA = (uint32_t)wid * 16 + (lane & 15);
    const uint32_t bnl = 8 * hiA + swz;
    const uint32_t qoffH = sb + QH_OFF + rowA * 256;
    const int r0 = q0 + wid * 16 + (lane >> 2);

    const char* kvbase = g_kv + ((size_t)((b * HCONST + h) * NKV)) * IMGSZ;

    // ---- issue K0,V0 + K1,V1 copies (ntiles >= 2 always) ----
    copy_img<KSZ>(sb + KBUF0, kvbase + KH_O, tid);
    copy_img<VSZ>(sb + VBUF0, kvbase + VTH_O, tid);
    CP_COMMIT();
    copy_img<KSZ>(sb + KBUF0 + KSZ, kvbase + IMGSZ + KH_O, tid);
    copy_img<VSZ>(sb + VBUF0 + VSZ, kvbase + IMGSZ + VTH_O, tid);
    CP_COMMIT();

    // ---- convert Q tile to fp16 (scale*log2e folded), overlaps copies ----
    {
        const float* qg = Q + ((size_t)(b * S + q0)) * rs + (size_t)h * DH;
        #pragma unroll
        for (int it = 0; it < 16; it++) {
            int idx = tid + NT * it;                 // 0..2047
            int r = idx >> 5, c4 = idx & 31;
            float4 v = *(const float4*)(qg + (size_t)r * rs + c4 * 4);
            uint32_t w0 = pack_h2(v.x * SCALE2, v.y * SCALE2);
            uint32_t w1 = pack_h2(v.z * SCALE2, v.w * SCALE2);
            uint32_t o = (uint32_t)r * 256 + ((((uint32_t)(c4 >> 1)) ^ (r & 7)) << 4) + (c4 & 1) * 8;
            *(uint2*)(smem + QH_OFF + o) = make_uint2(w0, w1);
        }
    }
    __syncthreads();   // Q smem complete

    // ---- load Q fragments into registers ONCE (tile-invariant) ----
    uint32_t qF[32];
    #pragma unroll
    for (int ks = 0; ks < 8; ks++)
        ldsm4(qF + 4 * ks, qoffH + (((((uint32_t)ks << 1) | hiA) ^ swz) << 4));

    CP_WAIT0();
    __syncthreads();

    float oacc[16][4];
    #pragma unroll
    for (int t = 0; t < 16; t++)
        #pragma unroll
        for (int e = 0; e < 4; e++) oacc[t][e] = 0.0f;
    float l0 = 0.0f, l1 = 0.0f;
    uint32_t pF[8];
    float sacc[4][4];

    // ---- prologue: QK(0) ----
    {
        const uint32_t kb_ = sb + KBUF0 + bnl * 256;   // K buf 0
        qk_ks<true>(sacc, qF + 0, kb_, 0, swz, kh8);
        #pragma unroll
        for (int ks = 1; ks < 8; ks++)
            qk_ks<false>(sacc, qF + 4 * ks, kb_, ks, swz, kh8);
    }
    __syncthreads();   // all warps done with Kbuf0 before K(2) copy overwrites it

    // ---- main loop: single barrier per tile; K double, V triple buffered ----
    int vm0 = 0, vm1 = 1, vm2 = 2;   // Vbuf indices of tiles j, j+1, j+2
    for (int j = 0; j < ntiles - 1; j++) {
        const uint32_t kb_ = sb + KBUF0 + (uint32_t)((j + 1) & 1) * KSZ + bnl * 256;  // K(j+1)
        const uint32_t vb_ = sb + VBUF0 + (uint32_t)vm0 * VSZ + bnl * 80 + kh8 * 16;  // V(j)
        const bool more2 = (j + 2 < ntiles);
        const char* g2 = kvbase + (size_t)(j + 2) * IMGSZ;
        const int n0 = j * BN;

        if (more2)
            copy_img<KSZ>(sb + KBUF0 + (uint32_t)(j & 1) * KSZ, g2 + KH_O, tid);
        CP_COMMIT();
        if (more2)
            copy_img<VSZ>(sb + VBUF0 + (uint32_t)vm2 * VSZ, g2 + VTH_O, tid);
        CP_COMMIT();

        // softmax(j): consumes sacc, fills pF
        softmax_tile(sacc, pF, l0, l1, n0, r0, causal, lane);

        qk_ks<true>(sacc, qF + 0,  kb_, 0, swz, kh8);   pv_s(oacc, pF + 0, vb_, 0);
        qk_ks<false>(sacc, qF + 4,  kb_, 1, swz, kh8);  pv_s(oacc, pF + 4, vb_, 1);
        qk_ks<false>(sacc, qF + 8,  kb_, 2, swz, kh8);
        qk_ks<false>(sacc, qF + 12, kb_, 3, swz, kh8);
        qk_ks<false>(sacc, qF + 16, kb_, 4, swz, kh8);
        qk_ks<false>(sacc, qF + 20, kb_, 5, swz, kh8);
        qk_ks<false>(sacc, qF + 24, kb_, 6, swz, kh8);
        qk_ks<false>(sacc, qF + 28, kb_, 7, swz, kh8);

        int tmp = vm0; vm0 = vm1; vm1 = vm2; vm2 = tmp;

        CP_WAIT1();        // K(j+2) group landed (V group may still fly)
        __syncthreads();   // single barrier per tile
    }

    // ---- tail: softmax + PV of tile (ntiles-1) ----
    {
        CP_WAIT0();        // ensure V(ntiles-1) landed
        const uint32_t vb_ = sb + VBUF0 + (uint32_t)vm0 * VSZ + bnl * 80 + kh8 * 16;
        const int n0 = (ntiles - 1) * BN;
        softmax_tile(sacc, pF, l0, l1, n0, r0, causal, lane);
        pv_s(oacc, pF + 0, vb_, 0);
        pv_s(oacc, pF + 4, vb_, 1);
    }

    // ---- epilogue ----
    l0 += __shfl_xor_sync(0xffffffffu, l0, 1);
    l0 += __shfl_xor_sync(0xffffffffu, l0, 2);
    l1 += __shfl_xor_sync(0xffffffffu, l1, 1);
    l1 += __shfl_xor_sync(0xffffffffu, l1, 2);
    const float i0 = 1.0f / l0, i1 = 1.0f / l1;

    float* o0 = O + ((size_t)(b * S + r0)) * rs + (size_t)h * DH;
    float* o1 = O + ((size_t)(b * S + r0 + 8)) * rs + (size_t)h * DH;
    const int cofs = 2 * (lane & 3);
    #pragma unroll
    for (int t = 0; t < 16; t++) {
        *(float2*)(o0 + 8 * t + cofs) = make_float2(oacc[t][0] * i0, oacc[t][1] * i0);
        *(float2*)(o1 + 8 * t + cofs) = make_float2(oacc[t][2] * i1, oacc[t][3] * i1);
    }
}

extern "C" void kernel_launch(void* const* d_in, const int* in_sizes, int n_in,
                              void* d_out, int out_size) {
    const float* q = (const float*)d_in[0];
    const float* k = (const float*)d_in[1];
    const float* v = (const float*)d_in[2];
    const int* causal = (const int*)d_in[3];
    float* out = (float*)d_out;

    const int B = 2, H = 16, D = 128;
    const int S = in_sizes[0] / (B * H * D);   // 2048

    dim3 pgrid(S / BN, H, B);
    kv_prepass<<<pgrid, PNT>>>(k, v, S, H);

    cudaFuncSetAttribute(fa_hmma13, cudaFuncAttributeMaxDynamicSharedMemorySize, SMEM_TOTAL);
    dim3 grid(S / BM, H, B);
    fa_hmma13<<<grid, NT, SMEM_TOTAL>>>(q, causal, out, S, H);
}